// round 13
// baseline (speedup 1.0000x reference)
#include <cuda_runtime.h>

// CtaPostAttnMixer: 4-step fixed-boundary heat diffusion along seq dim.
// x: (B=4, L=8192, D=1024) fp32.
//
// Interior rows: closed-form 9-tap convolution (taps of
// (0.1 s^-1 + 0.8 + 0.1 s)^4). Boundary rows: explicit 4-step iteration on an
// 8-row edge window, fused into dedicated edge blocks.
//
// R13: anti-thrash L2 partitioning. x is replay-invariant but 128MB vs 126MB
// L2 => pure LRU circular scan thrashes (0% hits), so steady state pays the
// full 256MB/iter mixed stream (~5.2TB/s => 49.3us floor seen in R4-R12).
// Protect 75% of x rows (8-row granules, default loads => resident across
// replays); stream the other 25% with __ldcs and ALL y stores with __stcs
// (evict-first), so streaming traffic recycles its own lines. Expected
// steady-state DRAM/iter ~170MB instead of 256MB.

constexpr int B  = 4;
constexpr int L  = 8192;
constexpr int D  = 1024;
constexpr int D4 = D / 4;            // float4 lanes per row
constexpr int L_CHUNK = 56;          // rows per block (interior)
constexpr int NCHUNK  = 148;         // 148 chunks x 4 batches = 592 blocks
constexpr int GROUP   = 4;           // rows per pipelined group (MLP depth)

// Taps of ((1-2a) + a*s + a*s^-1)^4 with a = 0.1 (symmetric, sums to 1)
constexpr float T0 = 0.0001f;
constexpr float T1 = 0.0032f;
constexpr float T2 = 0.0388f;
constexpr float T3 = 0.2144f;
constexpr float T4 = 0.4870f;

// Row-granular cache-policy split: rows whose ((l>>3)&3)==3 are the streamed
// 25%; the rest are the protected 75% (kept L2-resident across graph replays).
__device__ __forceinline__ bool streamed_row(int l) {
    return ((l >> 3) & 3) == 3;
}

__device__ __forceinline__ float4 load_x(const float4* p, int l) {
    return streamed_row(l) ? __ldcs(p) : *p;
}

__device__ __forceinline__ float4 conv9(const float4* w)
{
    float4 o;
    o.x = T4 * w[4].x + T3 * (w[3].x + w[5].x) + T2 * (w[2].x + w[6].x)
        + T1 * (w[1].x + w[7].x) + T0 * (w[0].x + w[8].x);
    o.y = T4 * w[4].y + T3 * (w[3].y + w[5].y) + T2 * (w[2].y + w[6].y)
        + T1 * (w[1].y + w[7].y) + T0 * (w[0].y + w[8].y);
    o.z = T4 * w[4].z + T3 * (w[3].z + w[5].z) + T2 * (w[2].z + w[6].z)
        + T1 * (w[1].z + w[7].z) + T0 * (w[0].z + w[8].z);
    o.w = T4 * w[4].w + T3 * (w[3].w + w[5].w) + T2 * (w[2].w + w[6].w)
        + T1 * (w[1].w + w[7].w) + T0 * (w[0].w + w[8].w);
    return o;
}

__global__ __launch_bounds__(256, 4) void mixer_kernel(
    const float* __restrict__ x, float* __restrict__ y)
{
    const int d4    = threadIdx.x;       // 0..255 (float4 column)
    const int chunk = blockIdx.x;        // 0..NCHUNK-1
    const int b     = blockIdx.y;        // 0..B-1

    const size_t base = (size_t)b * L * D;
    const float4* __restrict__ xb = reinterpret_cast<const float4*>(x + base) + d4;
    float4*       __restrict__ yb = reinterpret_cast<float4*>(y + base) + d4;

    const int l0   = 4 + chunk * L_CHUNK;
    int lend = l0 + L_CHUNK;
    if (lend > L - 4) lend = L - 4;

    // ---- Interior: 9-row sliding window, 4-deep prefetch per group ----
    if (l0 < lend) {
        float4 w[9];
#pragma unroll
        for (int k = 0; k < 9; ++k)
            w[k] = load_x(&xb[(size_t)(l0 - 4 + k) * D4], l0 - 4 + k);

        int l = l0;
#pragma unroll 1
        for (; l < lend; l += GROUP) {
            // Issue GROUP independent loads back-to-back (rows l+5 .. l+8),
            // clamped at L-1 (clamped values never reach an emitted output).
            float4 p[GROUP];
#pragma unroll
            for (int j = 0; j < GROUP; ++j) {
                int idx = l + 5 + j;
                if (idx > L - 1) idx = L - 1;
                p[j] = load_x(&xb[(size_t)idx * D4], idx);
            }

#pragma unroll
            for (int j = 0; j < GROUP; ++j) {
                __stcs(&yb[(size_t)(l + j) * D4], conv9(w));  // evict-first
#pragma unroll
                for (int k = 0; k < 8; ++k) w[k] = w[k + 1];
                w[8] = p[j];
            }
        }
    }

    // ---- Fused boundary: 4-step explicit iteration on 8-row edge window ----
    const bool left  = (chunk == 0);
    const bool right = (chunk == NCHUNK - 1);   // chunk 147: no interior rows
    if (left || right) {
        const int e0 = left ? 0 : (L - 8);

        float4 e[8];
#pragma unroll
        for (int k = 0; k < 8; ++k)
            e[k] = load_x(&xb[(size_t)(e0 + k) * D4], e0 + k);

        const float a = 0.1f;
#pragma unroll
        for (int s = 0; s < 4; ++s) {
            float4 prev = e[0];
#pragma unroll
            for (int i = 1; i < 7; ++i) {
                float4 cur = e[i];
                float4 nb  = e[i + 1];
                float4 nv;
                nv.x = cur.x + a * (nb.x - 2.0f * cur.x + prev.x);
                nv.y = cur.y + a * (nb.y - 2.0f * cur.y + prev.y);
                nv.z = cur.z + a * (nb.z - 2.0f * cur.z + prev.z);
                nv.w = cur.w + a * (nb.w - 2.0f * cur.w + prev.w);
                e[i] = nv;
                prev = cur;
            }
        }

        // Left edge: rows 0..3 (e[0] is the fixed boundary, emitted as-is);
        // right edge: rows L-4..L-1 (e[7] fixed).
        const int wbeg = left ? 0 : 4;
#pragma unroll
        for (int k = 0; k < 4; ++k)
            __stcs(&yb[(size_t)(e0 + wbeg + k) * D4], e[wbeg + k]);
    }
}

extern "C" void kernel_launch(void* const* d_in, const int* in_sizes, int n_in,
                              void* d_out, int out_size)
{
    const float* x = (const float*)d_in[0];
    float*       y = (float*)d_out;

    mixer_kernel<<<dim3(NCHUNK, B), 256>>>(x, y);
}

// round 17
// speedup vs baseline: 1.0645x; 1.0645x over previous
#include <cuda_runtime.h>
#include <cstdint>

// CtaPostAttnMixer: 4-step fixed-boundary heat diffusion along seq dim.
// x: (B=4, L=8192, D=1024) fp32.
//
// Interior rows: closed-form 9-tap convolution (taps of
// (0.1 s^-1 + 0.8 + 0.1 s)^4). Boundary rows: explicit 4-step iteration on an
// 8-row edge window, fused into dedicated edge blocks.
//
// R14 (resubmitted after R16 infra failure): R4 load structure + BULK WRITE
// BURSTS. Outputs for each 4-row group (16KB, contiguous in global) are
// staged in smem and emitted with a single cp.async.bulk S2G by one thread
// (double-buffered). Targets DRAM mixed-stream efficiency: write traffic
// becomes few fat contiguous bursts instead of ~600 interleaved 128B line
// streams. Loads unchanged (plain LDG, 4-deep register prefetch).

constexpr int B  = 4;
constexpr int L  = 8192;
constexpr int D  = 1024;
constexpr int D4 = D / 4;            // float4 lanes per row
constexpr int L_CHUNK = 56;          // rows per block (interior)
constexpr int NCHUNK  = 148;         // 148 chunks x 4 batches = 592 blocks
constexpr int GROUP   = 4;           // rows per group (prefetch + store burst)
constexpr int STAGE_F4    = GROUP * D4;          // 1024 float4 = 16KB
constexpr int STAGE_BYTES = GROUP * D * 4;       // 16384

// Taps of ((1-2a) + a*s + a*s^-1)^4 with a = 0.1 (symmetric, sums to 1)
constexpr float T0 = 0.0001f;
constexpr float T1 = 0.0032f;
constexpr float T2 = 0.0388f;
constexpr float T3 = 0.2144f;
constexpr float T4 = 0.4870f;

// ---------------- PTX helpers ----------------
__device__ __forceinline__ uint32_t smem_u32(const void* p) {
    uint32_t r;
    asm("{ .reg .u64 t; cvta.to.shared.u64 t, %1; cvt.u32.u64 %0, t; }"
        : "=r"(r) : "l"(p));
    return r;
}
__device__ __forceinline__ void bulk_s2g(void* gdst, uint32_t ssrc, uint32_t bytes) {
    asm volatile(
        "cp.async.bulk.global.shared::cta.bulk_group [%0], [%1], %2;"
        :: "l"(gdst), "r"(ssrc), "r"(bytes) : "memory");
}
__device__ __forceinline__ void bulk_commit() {
    asm volatile("cp.async.bulk.commit_group;" ::: "memory");
}
template <int N>
__device__ __forceinline__ void bulk_wait_read() {
    asm volatile("cp.async.bulk.wait_group.read %0;" :: "n"(N) : "memory");
}
template <int N>
__device__ __forceinline__ void bulk_wait() {
    asm volatile("cp.async.bulk.wait_group %0;" :: "n"(N) : "memory");
}
__device__ __forceinline__ void fence_proxy_async_cta() {
    asm volatile("fence.proxy.async.shared::cta;" ::: "memory");
}

// ---------------- math ----------------
__device__ __forceinline__ float4 conv9(const float4* w)
{
    float4 o;
    o.x = T4 * w[4].x + T3 * (w[3].x + w[5].x) + T2 * (w[2].x + w[6].x)
        + T1 * (w[1].x + w[7].x) + T0 * (w[0].x + w[8].x);
    o.y = T4 * w[4].y + T3 * (w[3].y + w[5].y) + T2 * (w[2].y + w[6].y)
        + T1 * (w[1].y + w[7].y) + T0 * (w[0].y + w[8].y);
    o.z = T4 * w[4].z + T3 * (w[3].z + w[5].z) + T2 * (w[2].z + w[6].z)
        + T1 * (w[1].z + w[7].z) + T0 * (w[0].z + w[8].z);
    o.w = T4 * w[4].w + T3 * (w[3].w + w[5].w) + T2 * (w[2].w + w[6].w)
        + T1 * (w[1].w + w[7].w) + T0 * (w[0].w + w[8].w);
    return o;
}

__global__ __launch_bounds__(256, 4) void mixer_kernel(
    const float* __restrict__ x, float* __restrict__ y)
{
    // Two 16KB staging buffers; layout matches global (row-major, 4 rows).
    __shared__ float4 stage[2][STAGE_F4];

    const int tid   = threadIdx.x;       // 0..255 (float4 column)
    const int chunk = blockIdx.x;        // 0..NCHUNK-1
    const int b     = blockIdx.y;        // 0..B-1

    const size_t base = (size_t)b * L * D;
    const float4* __restrict__ xb = reinterpret_cast<const float4*>(x + base) + tid;
    float4*       __restrict__ yb = reinterpret_cast<float4*>(y + base);

    const int l0   = 4 + chunk * L_CHUNK;
    int lend = l0 + L_CHUNK;
    if (lend > L - 4) lend = L - 4;

    const uint32_t st0 = smem_u32(&stage[0][0]);
    const uint32_t st1 = smem_u32(&stage[1][0]);

    // ---- Interior: 9-row window, 4-deep prefetch, 16KB bulk store bursts ----
    if (l0 < lend) {
        float4 w[9];
#pragma unroll
        for (int k = 0; k < 9; ++k)
            w[k] = xb[(size_t)(l0 - 4 + k) * D4];

        int g = 0;
#pragma unroll 1
        for (int l = l0; l < lend; l += GROUP, ++g) {
            // Prefetch next halo rows (l+5 .. l+8), clamped at L-1 (clamped
            // values never reach an emitted output).
            float4 p[GROUP];
#pragma unroll
            for (int j = 0; j < GROUP; ++j) {
                int idx = l + 5 + j;
                if (idx > L - 1) idx = L - 1;
                p[j] = xb[(size_t)idx * D4];
            }

            const int buf = g & 1;
            // Before overwriting this staging buffer, its bulk store issued
            // two groups ago must have finished READING smem.
            if (tid == 0 && g >= 2) bulk_wait_read<1>();
            __syncthreads();

            float4* sp = stage[buf] + tid;
#pragma unroll
            for (int j = 0; j < GROUP; ++j) {
                sp[j * D4] = conv9(w);
#pragma unroll
                for (int k = 0; k < 8; ++k) w[k] = w[k + 1];
                w[8] = p[j];
            }

            __syncthreads();   // all STS visible before the async-proxy read
            if (tid == 0) {
                fence_proxy_async_cta();
                bulk_s2g(yb + (size_t)l * D4,
                         buf ? st1 : st0, STAGE_BYTES);
                bulk_commit();
            }
        }

        if (tid == 0) bulk_wait<0>();   // drain before block exit
    }

    // ---- Fused boundary: 4-step explicit iteration on 8-row edge window ----
    const bool left  = (chunk == 0);
    const bool right = (chunk == NCHUNK - 1);   // chunk 147: no interior rows
    if (left || right) {
        const int e0 = left ? 0 : (L - 8);

        float4 e[8];
#pragma unroll
        for (int k = 0; k < 8; ++k)
            e[k] = xb[(size_t)(e0 + k) * D4];

        const float a = 0.1f;
#pragma unroll
        for (int s = 0; s < 4; ++s) {
            float4 prev = e[0];
#pragma unroll
            for (int i = 1; i < 7; ++i) {
                float4 cur = e[i];
                float4 nb  = e[i + 1];
                float4 nv;
                nv.x = cur.x + a * (nb.x - 2.0f * cur.x + prev.x);
                nv.y = cur.y + a * (nb.y - 2.0f * cur.y + prev.y);
                nv.z = cur.z + a * (nb.z - 2.0f * cur.z + prev.z);
                nv.w = cur.w + a * (nb.w - 2.0f * cur.w + prev.w);
                e[i] = nv;
                prev = cur;
            }
        }

        // Left edge: rows 0..3 (e[0] is the fixed boundary, emitted as-is);
        // right edge: rows L-4..L-1 (e[7] fixed).
        const int wbeg = left ? 0 : 4;
#pragma unroll
        for (int k = 0; k < 4; ++k)
            yb[(size_t)(e0 + wbeg + k) * D4 + tid] = e[wbeg + k];
    }
}

extern "C" void kernel_launch(void* const* d_in, const int* in_sizes, int n_in,
                              void* d_out, int out_size)
{
    const float* x = (const float*)d_in[0];
    float*       y = (float*)d_out;

    mixer_kernel<<<dim3(NCHUNK, B), 256>>>(x, y);
}